// round 6
// baseline (speedup 1.0000x reference)
#include <cuda_runtime.h>
#include <cuda_bf16.h>
#include <cstdint>

#define NN 50000
#define DD 128
#define EE 800000

// ---------------- scratch (static device globals: no allocation) ----------------
__device__ __align__(16) float g_y1[NN * DD];
__device__ __align__(16) float g_y2[NN * DD];
__device__ __align__(16) float g_stats[512];   // sum1, sq1, sum2, sq2 (self-zeroing)
__device__ __align__(16) float g_s1[DD];       // inner BN scale/shift
__device__ __align__(16) float g_t1[DD];
__device__ __align__(16) float g_s2[DD];       // outer BN scale/shift
__device__ __align__(16) float g_t2[DD];
__device__ int g_is64;
// bf16 weight images, W^T as [N][K] row-major: 6 matrices, hi+lo split
__device__ __align__(16) unsigned short g_whi[6 * DD * DD];
__device__ __align__(16) unsigned short g_wlo[6 * DD * DD];
// CSR (edges bucketed by dst) — built once per launch
__device__ int g_deg[50176];
__device__ int g_scan[50176];
__device__ int g_off[50176];
__device__ int g_cursor[50176];
__device__ int g_bsum[64];
__device__ int g_srcs[EE];

__device__ __forceinline__ uint32_t smem_to_u32(const void* p) {
    uint32_t a;
    asm("{ .reg .u64 t; cvta.to.shared.u64 t, %1; cvt.u32.u64 %0, t; }" : "=r"(a) : "l"(p));
    return a;
}

#define LDMX4(r0, r1, r2, r3, addr) \
    asm volatile("ldmatrix.sync.aligned.m8n8.x4.shared.b16 {%0,%1,%2,%3}, [%4];" \
                 : "=r"(r0), "=r"(r1), "=r"(r2), "=r"(r3) : "r"(addr))

#define MMA16816(d, a, b) \
    asm volatile("mma.sync.aligned.m16n8k16.row.col.f32.bf16.bf16.f32 " \
                 "{%0,%1,%2,%3}, {%4,%5,%6,%7}, {%8,%9}, {%0,%1,%2,%3};" \
                 : "+f"((d)[0]), "+f"((d)[1]), "+f"((d)[2]), "+f"((d)[3]) \
                 : "r"((a)[0]), "r"((a)[1]), "r"((a)[2]), "r"((a)[3]), "r"((b)[0]), "r"((b)[1]))

// ---------------- detect edge_index dtype (int32 vs int64) ----------------
__global__ void detect_k(const int* __restrict__ ei32) {
    int is64 = 1;
#pragma unroll
    for (int i = 0; i < 8; i++)
        if (ei32[2 * i + 1] != 0) is64 = 0;
    g_is64 = is64;
}

// ---------------- weight prep: transpose to [N][K] + bf16 hi/lo split ----------------
__global__ void wprep_k(const float* __restrict__ W1, const float* __restrict__ W2) {
    int b = blockIdx.x;                      // 384 blocks
    int wi = b >> 6;
    int id = ((b & 63) << 8) + threadIdx.x;
    const float* W = (wi < 3) ? (W1 + (size_t)wi * 16384) : (W2 + (size_t)(wi - 3) * 16384);
    int k = id >> 7, n = id & 127;
    float v = W[k * 128 + n];
    __nv_bfloat16 hb = __float2bfloat16(v);
    __nv_bfloat16 lb = __float2bfloat16(v - __bfloat162float(hb));
    g_whi[(size_t)wi * 16384 + n * 128 + k] = __bfloat16_as_ushort(hb);
    g_wlo[(size_t)wi * 16384 + n * 128 + k] = __bfloat16_as_ushort(lb);
}

// ================= CSR build (once; edge_index is loop-invariant) =================
__global__ void zdeg_k() {                  // 196 x 256
    g_deg[blockIdx.x * 256 + threadIdx.x] = 0;
}
__global__ void count_k(const int* __restrict__ ei32) {   // 782 x 256, 4 edges/thread
    int base = (blockIdx.x * 256 + threadIdx.x) * 4;
    int lim = (base + 4 < EE) ? base + 4 : EE;
    for (int e = base; e < lim; e++) {
        int d = g_is64 ? ei32[2 * (EE + e)] : ei32[EE + e];
        atomicAdd(&g_deg[d], 1);
    }
}
__global__ void scan1_k() {                 // 49 x 1024
    __shared__ int sm[1024];
    int t = threadIdx.x;
    int gid = blockIdx.x * 1024 + t;
    int v = (gid < NN) ? g_deg[gid] : 0;
    sm[t] = v;
    __syncthreads();
    for (int o = 1; o < 1024; o <<= 1) {
        int tv = (t >= o) ? sm[t - o] : 0;
        __syncthreads();
        sm[t] += tv;
        __syncthreads();
    }
    g_scan[gid] = sm[t] - v;
    if (t == 1023) g_bsum[blockIdx.x] = sm[1023];
}
__global__ void scan2_k() {
    int run = 0;
    for (int i = 0; i < 49; i++) { int t = g_bsum[i]; g_bsum[i] = run; run += t; }
}
__global__ void scan3_k() {                 // 49 x 1024
    int gid = blockIdx.x * 1024 + threadIdx.x;
    int o = g_scan[gid] + g_bsum[blockIdx.x];
    g_off[gid] = o;
    g_cursor[gid] = o;
}
__global__ void fill_k(const int* __restrict__ ei32) {    // 782 x 256, 4 edges/thread
    int base = (blockIdx.x * 256 + threadIdx.x) * 4;
    int lim = (base + 4 < EE) ? base + 4 : EE;
    for (int e = base; e < lim; e++) {
        int s, d;
        if (g_is64) { s = ei32[2 * e]; d = ei32[2 * (EE + e)]; }
        else        { s = ei32[e];     d = ei32[EE + e]; }
        int pos = atomicAdd(&g_cursor[d], 1);
        g_srcs[pos] = s;
    }
}

// ---------------- common smem layout for GEMM kernels ----------------
#define TSTRIDE 136
#define TBYTES  (128 * TSTRIDE * 2)
#define BIAS_OFF 0
#define AHI_OFF  1024
#define ALO_OFF  (AHI_OFF + TBYTES)
#define BHI_OFF  (ALO_OFF + TBYTES)
#define BLO_OFF  (BHI_OFF + TBYTES)
#define STAT_OFF (BLO_OFF + TBYTES)
#define GEMM_SMEM (STAT_OFF + 1024)

// split float4 -> bf16 hi/lo packed pairs, store 8B each to AHI/ALO
__device__ __forceinline__ void split_store(char* smem, uint32_t off, float4 a) {
    float v[4] = {a.x, a.y, a.z, a.w};
    uint32_t h[2], l[2];
#pragma unroll
    for (int j = 0; j < 2; j++) {
        __nv_bfloat16 h0 = __float2bfloat16(v[2 * j]);
        __nv_bfloat16 h1 = __float2bfloat16(v[2 * j + 1]);
        __nv_bfloat16 l0 = __float2bfloat16(v[2 * j] - __bfloat162float(h0));
        __nv_bfloat16 l1 = __float2bfloat16(v[2 * j + 1] - __bfloat162float(h1));
        h[j] = ((uint32_t)__bfloat16_as_ushort(h1) << 16) | __bfloat16_as_ushort(h0);
        l[j] = ((uint32_t)__bfloat16_as_ushort(l1) << 16) | __bfloat16_as_ushort(l0);
    }
    *(uint2*)(smem + AHI_OFF + off) = make_uint2(h[0], h[1]);
    *(uint2*)(smem + ALO_OFF + off) = make_uint2(l[0], l[1]);
}

// ---- shared mainloop + epilogue (called from both GEMM kernels) ----
__device__ __forceinline__ void mma_main_epi(
    char* smem, uint32_t sb, int tid, int rowBase,
    float* __restrict__ Y, float* __restrict__ colsum, float* __restrict__ colsq)
{
    int wid = tid >> 5, lane = tid & 31;
    int wm = wid & 1, wn = wid >> 1;
    int m0 = wm * 64, n0 = wn * 32;

    float acc[4][4][4];
#pragma unroll
    for (int i = 0; i < 4; i++)
#pragma unroll
        for (int j = 0; j < 4; j++)
#pragma unroll
            for (int q = 0; q < 4; q++) acc[i][j][q] = 0.f;

    uint32_t aOff = (uint32_t)((m0 + (lane & 15)) * (TSTRIDE * 2) + (lane >> 4) * 16);
    uint32_t bOff = (uint32_t)((n0 + (lane & 7) + (lane >> 4) * 8) * (TSTRIDE * 2) + ((lane >> 3) & 1) * 16);

#pragma unroll
    for (int ks = 0; ks < 8; ks++) {
        uint32_t kByte = (uint32_t)(ks * 32);
        uint32_t ah[4][4], al[4][4], bh[4][2], bl[4][2];
#pragma unroll
        for (int i = 0; i < 4; i++) {
            uint32_t ad = sb + AHI_OFF + aOff + kByte + (uint32_t)(i * 16 * TSTRIDE * 2);
            LDMX4(ah[i][0], ah[i][1], ah[i][2], ah[i][3], ad);
        }
#pragma unroll
        for (int i = 0; i < 4; i++) {
            uint32_t ad = sb + ALO_OFF + aOff + kByte + (uint32_t)(i * 16 * TSTRIDE * 2);
            LDMX4(al[i][0], al[i][1], al[i][2], al[i][3], ad);
        }
#pragma unroll
        for (int jj = 0; jj < 2; jj++) {
            uint32_t bd = sb + BHI_OFF + bOff + kByte + (uint32_t)(jj * 16 * TSTRIDE * 2);
            uint32_t r0, r1, r2, r3;
            LDMX4(r0, r1, r2, r3, bd);
            bh[2 * jj][0] = r0; bh[2 * jj][1] = r1;
            bh[2 * jj + 1][0] = r2; bh[2 * jj + 1][1] = r3;
            bd = sb + BLO_OFF + bOff + kByte + (uint32_t)(jj * 16 * TSTRIDE * 2);
            LDMX4(r0, r1, r2, r3, bd);
            bl[2 * jj][0] = r0; bl[2 * jj][1] = r1;
            bl[2 * jj + 1][0] = r2; bl[2 * jj + 1][1] = r3;
        }
#pragma unroll
        for (int i = 0; i < 4; i++)
#pragma unroll
            for (int j = 0; j < 4; j++) MMA16816(acc[i][j], ah[i], bh[j]);
#pragma unroll
        for (int i = 0; i < 4; i++)
#pragma unroll
            for (int j = 0; j < 4; j++) MMA16816(acc[i][j], ah[i], bl[j]);
#pragma unroll
        for (int i = 0; i < 4; i++)
#pragma unroll
            for (int j = 0; j < 4; j++) MMA16816(acc[i][j], al[i], bh[j]);
    }

    // ---- epilogue: bias, store, fused BN stats ----
    float* scs = (float*)(smem + STAT_OFF);
    float* scq = scs + 128;
    int rq = lane >> 2, cq = (lane & 3) * 2;
    const float* bs = (const float*)(smem + BIAS_OFF);

    float ps[4][2], pq[4][2];
#pragma unroll
    for (int j = 0; j < 4; j++) { ps[j][0] = ps[j][1] = 0.f; pq[j][0] = pq[j][1] = 0.f; }

#pragma unroll
    for (int i = 0; i < 4; i++) {
        int r0g = rowBase + m0 + i * 16 + rq;
#pragma unroll
        for (int j = 0; j < 4; j++) {
            int cg = n0 + j * 8 + cq;
            float bx = bs[cg], by = bs[cg + 1];
            if (r0g < NN) {
                float v0 = acc[i][j][0] + bx, v1 = acc[i][j][1] + by;
                *(float2*)(Y + (size_t)r0g * DD + cg) = make_float2(v0, v1);
                ps[j][0] += v0; pq[j][0] += v0 * v0;
                ps[j][1] += v1; pq[j][1] += v1 * v1;
            }
            if (r0g + 8 < NN) {
                float v2 = acc[i][j][2] + bx, v3 = acc[i][j][3] + by;
                *(float2*)(Y + (size_t)(r0g + 8) * DD + cg) = make_float2(v2, v3);
                ps[j][0] += v2; pq[j][0] += v2 * v2;
                ps[j][1] += v3; pq[j][1] += v3 * v3;
            }
        }
    }
#pragma unroll
    for (int j = 0; j < 4; j++)
#pragma unroll
        for (int c = 0; c < 2; c++) {
#pragma unroll
            for (int m = 4; m <= 16; m <<= 1) {
                ps[j][c] += __shfl_xor_sync(0xFFFFFFFFu, ps[j][c], m);
                pq[j][c] += __shfl_xor_sync(0xFFFFFFFFu, pq[j][c], m);
            }
        }
    if (rq == 0) {
#pragma unroll
        for (int j = 0; j < 4; j++)
#pragma unroll
            for (int c = 0; c < 2; c++) {
                atomicAdd(&scs[n0 + j * 8 + cq + c], ps[j][c]);
                atomicAdd(&scq[n0 + j * 8 + cq + c], pq[j][c]);
            }
    }
    __syncthreads();
    if (tid < 128) {
        atomicAdd(&colsum[tid], scs[tid]);
        atomicAdd(&colsq[tid],  scq[tid]);
    }
}

__device__ __forceinline__ void load_btiles(char* smem, int tid,
    const unsigned short* __restrict__ whi, const unsigned short* __restrict__ wlo)
{
    const uint4* sh = (const uint4*)whi;
    const uint4* sl = (const uint4*)wlo;
#pragma unroll
    for (int i = 0; i < 8; i++) {
        int id = i * 256 + tid;
        int r = id >> 4, c16 = id & 15;
        uint32_t dst = (uint32_t)(r * (TSTRIDE * 2) + c16 * 16);
        *(uint4*)(smem + BHI_OFF + dst) = sh[id];
        *(uint4*)(smem + BLO_OFF + dst) = sl[id];
    }
}

// ---------------- GEMM1: fused CSR gather + GIN combine + GEMM + BN stats ----------
// TRANS=0 (layer 0): msg = relu(x[src]),          own = x[row]
// TRANS=1 (layer>0): msg = relu(y2[src]*s2+t2) ,  own = relu(y2[row]*s2+t2)
// A[row] = (1+eps)*own + sum(msg) ; Y = A @ W1 + b1
template <int TRANS>
__global__ void __launch_bounds__(256, 1) gemm1_k(
    const float* __restrict__ P, const float* __restrict__ epsp, int layer,
    const unsigned short* __restrict__ whi, const unsigned short* __restrict__ wlo,
    const float* __restrict__ bias, float* __restrict__ Y,
    float* __restrict__ colsum, float* __restrict__ colsq)
{
    extern __shared__ __align__(16) char smem[];
    uint32_t sb = smem_to_u32(smem);
    int tid = threadIdx.x;
    int wid = tid >> 5, lane = tid & 31;
    int rowBase = blockIdx.x * 128;

    if (tid < 128) *(float*)(smem + BIAS_OFF + tid * 4) = bias[tid];
    ((float*)(smem + STAT_OFF))[tid] = 0.f;

    load_btiles(smem, tid, whi, wlo);

    float epsv = 1.0f + epsp[layer];
    float4 sv, tv;
    if (TRANS) {
        sv = *(const float4*)(g_s2 + lane * 4);
        tv = *(const float4*)(g_t2 + lane * 4);
    }

    // each warp: 16 rows; lane owns 4 feature cols (lane*4)
#pragma unroll 1
    for (int r = 0; r < 16; r++) {
        int row = wid * 16 + r;
        int gr = rowBase + row;
        float4 av = make_float4(0.f, 0.f, 0.f, 0.f);
        if (gr < NN) {
            int beg = g_off[gr], end = g_off[gr + 1];
            float4 acc = make_float4(0.f, 0.f, 0.f, 0.f);
            int e = beg;
            for (; e + 3 < end; e += 4) {
                int s0 = g_srcs[e], s1 = g_srcs[e + 1], s2i = g_srcs[e + 2], s3 = g_srcs[e + 3];
                float4 v0 = *(const float4*)(P + (size_t)s0 * DD + lane * 4);
                float4 v1 = *(const float4*)(P + (size_t)s1 * DD + lane * 4);
                float4 v2 = *(const float4*)(P + (size_t)s2i * DD + lane * 4);
                float4 v3 = *(const float4*)(P + (size_t)s3 * DD + lane * 4);
                if (TRANS) {
                    v0.x = fmaf(v0.x, sv.x, tv.x); v0.y = fmaf(v0.y, sv.y, tv.y);
                    v0.z = fmaf(v0.z, sv.z, tv.z); v0.w = fmaf(v0.w, sv.w, tv.w);
                    v1.x = fmaf(v1.x, sv.x, tv.x); v1.y = fmaf(v1.y, sv.y, tv.y);
                    v1.z = fmaf(v1.z, sv.z, tv.z); v1.w = fmaf(v1.w, sv.w, tv.w);
                    v2.x = fmaf(v2.x, sv.x, tv.x); v2.y = fmaf(v2.y, sv.y, tv.y);
                    v2.z = fmaf(v2.z, sv.z, tv.z); v2.w = fmaf(v2.w, sv.w, tv.w);
                    v3.x = fmaf(v3.x, sv.x, tv.x); v3.y = fmaf(v3.y, sv.y, tv.y);
                    v3.z = fmaf(v3.z, sv.z, tv.z); v3.w = fmaf(v3.w, sv.w, tv.w);
                }
                acc.x += fmaxf(v0.x, 0.f) + fmaxf(v1.x, 0.f) + fmaxf(v2.x, 0.f) + fmaxf(v3.x, 0.f);
                acc.y += fmaxf(v0.y, 0.f) + fmaxf(v1.y, 0.f) + fmaxf(v2.y, 0.f) + fmaxf(v3.y, 0.f);
                acc.z += fmaxf(v0.z, 0.f) + fmaxf(v1.z, 0.f) + fmaxf(v2.z, 0.f) + fmaxf(v3.z, 0.f);
                acc.w += fmaxf(v0.w, 0.f) + fmaxf(v1.w, 0.f) + fmaxf(v2.w, 0.f) + fmaxf(v3.w, 0.f);
            }
            for (; e < end; e++) {
                int s0 = g_srcs[e];
                float4 v0 = *(const float4*)(P + (size_t)s0 * DD + lane * 4);
                if (TRANS) {
                    v0.x = fmaf(v0.x, sv.x, tv.x); v0.y = fmaf(v0.y, sv.y, tv.y);
                    v0.z = fmaf(v0.z, sv.z, tv.z); v0.w = fmaf(v0.w, sv.w, tv.w);
                }
                acc.x += fmaxf(v0.x, 0.f); acc.y += fmaxf(v0.y, 0.f);
                acc.z += fmaxf(v0.z, 0.f); acc.w += fmaxf(v0.w, 0.f);
            }
            // own row
            float4 o = *(const float4*)(P + (size_t)gr * DD + lane * 4);
            if (TRANS) {
                o.x = fmaxf(fmaf(o.x, sv.x, tv.x), 0.f);
                o.y = fmaxf(fmaf(o.y, sv.y, tv.y), 0.f);
                o.z = fmaxf(fmaf(o.z, sv.z, tv.z), 0.f);
                o.w = fmaxf(fmaf(o.w, sv.w, tv.w), 0.f);
            }
            av.x = fmaf(epsv, o.x, acc.x);
            av.y = fmaf(epsv, o.y, acc.y);
            av.z = fmaf(epsv, o.z, acc.z);
            av.w = fmaf(epsv, o.w, acc.w);
        }
        split_store(smem, (uint32_t)(row * (TSTRIDE * 2) + lane * 8), av);
    }
    __syncthreads();

    mma_main_epi(smem, sb, tid, rowBase, Y, colsum, colsq);
}

// ---------------- GEMM2: A = relu(y1*s1+t1) ; Y = A @ W2 + b2 + BN stats ----------
__global__ void __launch_bounds__(256, 1) gemm2_k(
    const float* __restrict__ A0,
    const unsigned short* __restrict__ whi, const unsigned short* __restrict__ wlo,
    const float* __restrict__ bias, float* __restrict__ Y,
    float* __restrict__ colsum, float* __restrict__ colsq)
{
    extern __shared__ __align__(16) char smem[];
    uint32_t sb = smem_to_u32(smem);
    int tid = threadIdx.x;
    int rowBase = blockIdx.x * 128;

    if (tid < 128) *(float*)(smem + BIAS_OFF + tid * 4) = bias[tid];
    ((float*)(smem + STAT_OFF))[tid] = 0.f;

    load_btiles(smem, tid, whi, wlo);

#pragma unroll
    for (int it = 0; it < 8; it++) {
        int id = it * 256 + tid;
        int row = id >> 4;
        int col = (id & 15) * 8;
        int gr = rowBase + row;
        float4 a = make_float4(0.f, 0.f, 0.f, 0.f);
        float4 b = make_float4(0.f, 0.f, 0.f, 0.f);
        if (gr < NN) {
            float4 p0 = *(const float4*)(A0 + (size_t)gr * DD + col);
            float4 p1 = *(const float4*)(A0 + (size_t)gr * DD + col + 4);
            float4 s0 = *(const float4*)(g_s1 + col);
            float4 s1v = *(const float4*)(g_s1 + col + 4);
            float4 t0 = *(const float4*)(g_t1 + col);
            float4 t1v = *(const float4*)(g_t1 + col + 4);
            a.x = fmaxf(fmaf(p0.x, s0.x, t0.x), 0.f);
            a.y = fmaxf(fmaf(p0.y, s0.y, t0.y), 0.f);
            a.z = fmaxf(fmaf(p0.z, s0.z, t0.z), 0.f);
            a.w = fmaxf(fmaf(p0.w, s0.w, t0.w), 0.f);
            b.x = fmaxf(fmaf(p1.x, s1v.x, t1v.x), 0.f);
            b.y = fmaxf(fmaf(p1.y, s1v.y, t1v.y), 0.f);
            b.z = fmaxf(fmaf(p1.z, s1v.z, t1v.z), 0.f);
            b.w = fmaxf(fmaf(p1.w, s1v.w, t1v.w), 0.f);
        }
        uint32_t off = (uint32_t)(row * (TSTRIDE * 2) + col * 2);
        split_store(smem, off, a);
        split_store(smem, off + 8, b);
    }
    __syncthreads();

    mma_main_epi(smem, sb, tid, rowBase, Y, colsum, colsq);
}

// ---------------- BN scale/shift (reads stats bank, then zeroes it) ----------------
__global__ void bn_stats_k(float* __restrict__ cs, float* __restrict__ cq,
                           const float* __restrict__ g, const float* __restrict__ b,
                           float* __restrict__ sOut, float* __restrict__ tOut)
{
    int d = threadIdx.x;
    float su = cs[d], sq = cq[d];
    float mu  = su * (1.0f / NN);
    float var = sq * (1.0f / NN) - mu * mu;
    float sc  = g[d] * rsqrtf(var + 1e-5f);
    sOut[d] = sc;
    tOut[d] = b[d] - mu * sc;
    cs[d] = 0.f;      // self-zero for next layer (globals start zeroed)
    cq[d] = 0.f;
}

// ---------------- final output: out = y2*s2+t2 (no relu, last layer) ----------------
__global__ void finalize_k(float* __restrict__ out) {
    int i = blockIdx.x * 256 + threadIdx.x;   // 6250 * 256 = NN*DD/4
    int d4 = (i * 4) & 127;
    float4 v = ((const float4*)g_y2)[i];
    float4 s = *(const float4*)(g_s2 + d4);
    float4 t = *(const float4*)(g_t2 + d4);
    v.x = fmaf(v.x, s.x, t.x);
    v.y = fmaf(v.y, s.y, t.y);
    v.z = fmaf(v.z, s.z, t.z);
    v.w = fmaf(v.w, s.w, t.w);
    ((float4*)out)[i] = v;
}

extern "C" void kernel_launch(void* const* d_in, const int* in_sizes, int n_in,
                              void* d_out, int out_size)
{
    const float* x    = (const float*)d_in[0];
    const int*   ei32 = (const int*)d_in[1];
    const float* eps  = (const float*)d_in[2];
    const float* W1   = (const float*)d_in[3];
    const float* b1   = (const float*)d_in[4];
    const float* bn1g = (const float*)d_in[5];
    const float* bn1b = (const float*)d_in[6];
    const float* W2   = (const float*)d_in[7];
    const float* b2   = (const float*)d_in[8];
    const float* bn2g = (const float*)d_in[9];
    const float* bn2b = (const float*)d_in[10];

    float *y1p, *y2p, *statsp, *s1p, *t1p, *s2p, *t2p;
    unsigned short *whip, *wlop;
    cudaGetSymbolAddress((void**)&y1p,    g_y1);
    cudaGetSymbolAddress((void**)&y2p,    g_y2);
    cudaGetSymbolAddress((void**)&statsp, g_stats);
    cudaGetSymbolAddress((void**)&s1p,    g_s1);
    cudaGetSymbolAddress((void**)&t1p,    g_t1);
    cudaGetSymbolAddress((void**)&s2p,    g_s2);
    cudaGetSymbolAddress((void**)&t2p,    g_t2);
    cudaGetSymbolAddress((void**)&whip,   g_whi);
    cudaGetSymbolAddress((void**)&wlop,   g_wlo);

    cudaFuncSetAttribute(gemm1_k<0>, cudaFuncAttributeMaxDynamicSharedMemorySize, GEMM_SMEM);
    cudaFuncSetAttribute(gemm1_k<1>, cudaFuncAttributeMaxDynamicSharedMemorySize, GEMM_SMEM);
    cudaFuncSetAttribute(gemm2_k,    cudaFuncAttributeMaxDynamicSharedMemorySize, GEMM_SMEM);

    const int gemmBlocks = (NN + 127) / 128;   // 391

    // one-time prep
    detect_k<<<1, 1>>>(ei32);
    wprep_k<<<384, 256>>>(W1, W2);
    zdeg_k<<<196, 256>>>();
    count_k<<<782, 256>>>(ei32);
    scan1_k<<<49, 1024>>>();
    scan2_k<<<1, 1>>>();
    scan3_k<<<49, 1024>>>();
    fill_k<<<782, 256>>>(ei32);

    for (int l = 0; l < 3; l++) {
        if (l == 0)
            gemm1_k<0><<<gemmBlocks, 256, GEMM_SMEM>>>(x, eps, l,
                whip + (size_t)l * 16384, wlop + (size_t)l * 16384,
                b1 + (size_t)l * DD, y1p, statsp, statsp + 128);
        else
            gemm1_k<1><<<gemmBlocks, 256, GEMM_SMEM>>>(y2p, eps, l,
                whip + (size_t)l * 16384, wlop + (size_t)l * 16384,
                b1 + (size_t)l * DD, y1p, statsp, statsp + 128);
        bn_stats_k<<<1, 128>>>(statsp, statsp + 128,
                               bn1g + (size_t)l * DD, bn1b + (size_t)l * DD, s1p, t1p);
        gemm2_k<<<gemmBlocks, 256, GEMM_SMEM>>>(y1p,
            whip + (size_t)(3 + l) * 16384, wlop + (size_t)(3 + l) * 16384,
            b2 + (size_t)l * DD, y2p, statsp + 256, statsp + 384);
        bn_stats_k<<<1, 128>>>(statsp + 256, statsp + 384,
                               bn2g + (size_t)l * DD, bn2b + (size_t)l * DD, s2p, t2p);
    }
    finalize_k<<<6250, 256>>>((float*)d_out);
}

// round 7
// speedup vs baseline: 1.5879x; 1.5879x over previous
#include <cuda_runtime.h>
#include <cuda_bf16.h>
#include <cstdint>

#define NN 50000
#define DD 128
#define EE 800000

// ---------------- scratch (static device globals: no allocation) ----------------
__device__ __align__(16) float g_agg[NN * DD];
__device__ __align__(16) float g_y1[NN * DD];
__device__ __align__(16) float g_y2[NN * DD];
__device__ __align__(16) float g_stats[512];   // sum1, sq1, sum2, sq2 (self-zeroing)
__device__ __align__(16) float g_s1[DD];       // inner BN scale/shift
__device__ __align__(16) float g_t1[DD];
__device__ __align__(16) float g_s2[DD];       // outer BN scale/shift
__device__ __align__(16) float g_t2[DD];
__device__ int g_is64;
// bf16 weight images, W^T as [N][K] row-major: 6 matrices, hi+lo split
__device__ __align__(16) unsigned short g_whi[6 * DD * DD];
__device__ __align__(16) unsigned short g_wlo[6 * DD * DD];
// CSR (edges bucketed by dst) — built once per launch
__device__ int g_deg[50176];
__device__ int g_scan[50176];
__device__ int g_off[50176];
__device__ int g_cursor[50176];
__device__ int g_bsum[64];
__device__ int g_srcs[EE];

__device__ __forceinline__ uint32_t smem_to_u32(const void* p) {
    uint32_t a;
    asm("{ .reg .u64 t; cvta.to.shared.u64 t, %1; cvt.u32.u64 %0, t; }" : "=r"(a) : "l"(p));
    return a;
}

#define LDMX4(r0, r1, r2, r3, addr) \
    asm volatile("ldmatrix.sync.aligned.m8n8.x4.shared.b16 {%0,%1,%2,%3}, [%4];" \
                 : "=r"(r0), "=r"(r1), "=r"(r2), "=r"(r3) : "r"(addr))

#define MMA16816(d, a, b) \
    asm volatile("mma.sync.aligned.m16n8k16.row.col.f32.bf16.bf16.f32 " \
                 "{%0,%1,%2,%3}, {%4,%5,%6,%7}, {%8,%9}, {%0,%1,%2,%3};" \
                 : "+f"((d)[0]), "+f"((d)[1]), "+f"((d)[2]), "+f"((d)[3]) \
                 : "r"((a)[0]), "r"((a)[1]), "r"((a)[2]), "r"((a)[3]), "r"((b)[0]), "r"((b)[1]))

// ---------------- detect edge_index dtype (int32 vs int64) ----------------
__global__ void detect_k(const int* __restrict__ ei32) {
    int is64 = 1;
#pragma unroll
    for (int i = 0; i < 8; i++)
        if (ei32[2 * i + 1] != 0) is64 = 0;
    g_is64 = is64;
}

// ---------------- weight prep: transpose to [N][K] + bf16 hi/lo split ----------------
__global__ void wprep_k(const float* __restrict__ W1, const float* __restrict__ W2) {
    int b = blockIdx.x;                      // 384 blocks
    int wi = b >> 6;
    int id = ((b & 63) << 8) + threadIdx.x;
    const float* W = (wi < 3) ? (W1 + (size_t)wi * 16384) : (W2 + (size_t)(wi - 3) * 16384);
    int k = id >> 7, n = id & 127;
    float v = W[k * 128 + n];
    __nv_bfloat16 hb = __float2bfloat16(v);
    __nv_bfloat16 lb = __float2bfloat16(v - __bfloat162float(hb));
    g_whi[(size_t)wi * 16384 + n * 128 + k] = __bfloat16_as_ushort(hb);
    g_wlo[(size_t)wi * 16384 + n * 128 + k] = __bfloat16_as_ushort(lb);
}

// ================= CSR build (once; edge_index is loop-invariant) =================
__global__ void zdeg_k() {                  // 196 x 256
    g_deg[blockIdx.x * 256 + threadIdx.x] = 0;
}
__global__ void count_k(const int* __restrict__ ei32) {   // 3125 x 256
    int e = blockIdx.x * 256 + threadIdx.x;
    if (e >= EE) return;
    int d = g_is64 ? ei32[2 * (EE + e)] : ei32[EE + e];
    atomicAdd(&g_deg[d], 1);
}
__global__ void scan1_k() {                 // 49 x 1024
    __shared__ int sm[1024];
    int t = threadIdx.x;
    int gid = blockIdx.x * 1024 + t;
    int v = (gid < NN) ? g_deg[gid] : 0;
    sm[t] = v;
    __syncthreads();
    for (int o = 1; o < 1024; o <<= 1) {
        int tv = (t >= o) ? sm[t - o] : 0;
        __syncthreads();
        sm[t] += tv;
        __syncthreads();
    }
    g_scan[gid] = sm[t] - v;
    if (t == 1023) g_bsum[blockIdx.x] = sm[1023];
}
__global__ void scan2_k() {
    int run = 0;
    for (int i = 0; i < 49; i++) { int t = g_bsum[i]; g_bsum[i] = run; run += t; }
}
__global__ void scan3_k() {                 // 49 x 1024
    int gid = blockIdx.x * 1024 + threadIdx.x;
    int o = g_scan[gid] + g_bsum[blockIdx.x];
    g_off[gid] = o;
    g_cursor[gid] = o;
}
__global__ void fill_k(const int* __restrict__ ei32) {    // 3125 x 256
    int e = blockIdx.x * 256 + threadIdx.x;
    if (e >= EE) return;
    int s, d;
    if (g_is64) { s = ei32[2 * e]; d = ei32[2 * (EE + e)]; }
    else        { s = ei32[e];     d = ei32[EE + e]; }
    int pos = atomicAdd(&g_cursor[d], 1);
    g_srcs[pos] = s;
}

// ------- aggregation: per-node gather + register sum; optional fused prev-layer BN ----
// TRANS=0: msg = relu(P[src]);  TRANS=1: msg = relu(P[src]*s2 + t2)
template <int TRANS>
__global__ void __launch_bounds__(256) agg_k(const float* __restrict__ P) {
    int w = blockIdx.x * 8 + (threadIdx.x >> 5);  // 6250 blocks -> 50000 warps
    int lane = threadIdx.x & 31;
    int s = g_off[w], t = g_off[w + 1];
    float4 sv, tv;
    if (TRANS) {
        sv = *(const float4*)(g_s2 + lane * 4);
        tv = *(const float4*)(g_t2 + lane * 4);
    }
    float4 acc = make_float4(0.f, 0.f, 0.f, 0.f);
    int e = s;
    for (; e + 1 < t; e += 2) {
        int s0 = g_srcs[e], s1 = g_srcs[e + 1];
        float4 v0 = *(const float4*)(P + (size_t)s0 * DD + lane * 4);
        float4 v1 = *(const float4*)(P + (size_t)s1 * DD + lane * 4);
        if (TRANS) {
            v0.x = fmaf(v0.x, sv.x, tv.x); v0.y = fmaf(v0.y, sv.y, tv.y);
            v0.z = fmaf(v0.z, sv.z, tv.z); v0.w = fmaf(v0.w, sv.w, tv.w);
            v1.x = fmaf(v1.x, sv.x, tv.x); v1.y = fmaf(v1.y, sv.y, tv.y);
            v1.z = fmaf(v1.z, sv.z, tv.z); v1.w = fmaf(v1.w, sv.w, tv.w);
        }
        acc.x += fmaxf(v0.x, 0.f) + fmaxf(v1.x, 0.f);
        acc.y += fmaxf(v0.y, 0.f) + fmaxf(v1.y, 0.f);
        acc.z += fmaxf(v0.z, 0.f) + fmaxf(v1.z, 0.f);
        acc.w += fmaxf(v0.w, 0.f) + fmaxf(v1.w, 0.f);
    }
    if (e < t) {
        int s0 = g_srcs[e];
        float4 v0 = *(const float4*)(P + (size_t)s0 * DD + lane * 4);
        if (TRANS) {
            v0.x = fmaf(v0.x, sv.x, tv.x); v0.y = fmaf(v0.y, sv.y, tv.y);
            v0.z = fmaf(v0.z, sv.z, tv.z); v0.w = fmaf(v0.w, sv.w, tv.w);
        }
        acc.x += fmaxf(v0.x, 0.f);
        acc.y += fmaxf(v0.y, 0.f);
        acc.z += fmaxf(v0.z, 0.f);
        acc.w += fmaxf(v0.w, 0.f);
    }
    *(float4*)(g_agg + (size_t)w * DD + lane * 4) = acc;
}

// ---------------- HMMA GEMM (128x128x128, bf16-split, fused BN-stats epilogue) ----
// MODE 1: A = (1+eps)*own + agg ; own = P[row] (TRANS=0) or relu(P[row]*s2+t2) (TRANS=1)
// MODE 2: A = relu(y1*s1+t1)
#define TSTRIDE 136
#define TBYTES  (128 * TSTRIDE * 2)
#define BIAS_OFF 0
#define AHI_OFF  1024
#define ALO_OFF  (AHI_OFF + TBYTES)
#define BHI_OFF  (ALO_OFF + TBYTES)
#define BLO_OFF  (BHI_OFF + TBYTES)
#define STAT_OFF (BLO_OFF + TBYTES)
#define GEMM_SMEM (STAT_OFF + 1024)

template <int MODE, int TRANS>
__global__ void __launch_bounds__(256, 1) gemm_tc_k(
    const float* __restrict__ A0, const float* __restrict__ epsp, int layer,
    const unsigned short* __restrict__ whi, const unsigned short* __restrict__ wlo,
    const float* __restrict__ bias, float* __restrict__ Y,
    float* __restrict__ colsum, float* __restrict__ colsq)
{
    extern __shared__ __align__(16) char smem[];
    uint32_t sb = smem_to_u32(smem);
    int tid = threadIdx.x;
    int wid = tid >> 5, lane = tid & 31;
    int rowBase = blockIdx.x * 128;

    if (tid < 128) *(float*)(smem + BIAS_OFF + tid * 4) = bias[tid];
    ((float*)(smem + STAT_OFF))[tid] = 0.f;

    // ---- B tiles ----
    {
        const uint4* sh = (const uint4*)whi;
        const uint4* sl = (const uint4*)wlo;
#pragma unroll
        for (int i = 0; i < 8; i++) {
            int id = i * 256 + tid;
            int r = id >> 4, c16 = id & 15;
            uint32_t dst = (uint32_t)(r * (TSTRIDE * 2) + c16 * 16);
            *(uint4*)(smem + BHI_OFF + dst) = sh[id];
            *(uint4*)(smem + BLO_OFF + dst) = sl[id];
        }
    }

    // ---- A tile: fused transform + bf16 split ----
    float epsv = (MODE == 1) ? (1.0f + epsp[layer]) : 0.0f;
#pragma unroll
    for (int it = 0; it < 8; it++) {
        int id = it * 256 + tid;
        int row = id >> 4;
        int col = (id & 15) * 8;
        int gr = rowBase + row;
        float v[8];
#pragma unroll
        for (int j = 0; j < 8; j++) v[j] = 0.f;
        if (gr < NN) {
            float4 p0 = *(const float4*)(A0 + (size_t)gr * DD + col);
            float4 p1 = *(const float4*)(A0 + (size_t)gr * DD + col + 4);
            v[0] = p0.x; v[1] = p0.y; v[2] = p0.z; v[3] = p0.w;
            v[4] = p1.x; v[5] = p1.y; v[6] = p1.z; v[7] = p1.w;
            if (MODE == 1) {
                if (TRANS) {
#pragma unroll
                    for (int j = 0; j < 8; j++)
                        v[j] = fmaxf(fmaf(v[j], g_s2[col + j], g_t2[col + j]), 0.f);
                }
                float4 a0 = *(const float4*)(g_agg + (size_t)gr * DD + col);
                float4 a1 = *(const float4*)(g_agg + (size_t)gr * DD + col + 4);
                v[0] = fmaf(epsv, v[0], a0.x); v[1] = fmaf(epsv, v[1], a0.y);
                v[2] = fmaf(epsv, v[2], a0.z); v[3] = fmaf(epsv, v[3], a0.w);
                v[4] = fmaf(epsv, v[4], a1.x); v[5] = fmaf(epsv, v[5], a1.y);
                v[6] = fmaf(epsv, v[6], a1.z); v[7] = fmaf(epsv, v[7], a1.w);
            } else {
#pragma unroll
                for (int j = 0; j < 8; j++)
                    v[j] = fmaxf(fmaf(v[j], g_s1[col + j], g_t1[col + j]), 0.f);
            }
        }
        uint32_t h[4], l[4];
#pragma unroll
        for (int j = 0; j < 4; j++) {
            __nv_bfloat16 h0 = __float2bfloat16(v[2 * j]);
            __nv_bfloat16 h1 = __float2bfloat16(v[2 * j + 1]);
            __nv_bfloat16 l0 = __float2bfloat16(v[2 * j] - __bfloat162float(h0));
            __nv_bfloat16 l1 = __float2bfloat16(v[2 * j + 1] - __bfloat162float(h1));
            h[j] = ((uint32_t)__bfloat16_as_ushort(h1) << 16) | __bfloat16_as_ushort(h0);
            l[j] = ((uint32_t)__bfloat16_as_ushort(l1) << 16) | __bfloat16_as_ushort(l0);
        }
        uint32_t off = (uint32_t)(row * (TSTRIDE * 2) + col * 2);
        *(uint4*)(smem + AHI_OFF + off) = make_uint4(h[0], h[1], h[2], h[3]);
        *(uint4*)(smem + ALO_OFF + off) = make_uint4(l[0], l[1], l[2], l[3]);
    }
    __syncthreads();

    // ---- warp MMA mainloop ----
    int wm = wid & 1, wn = wid >> 1;
    int m0 = wm * 64, n0 = wn * 32;

    float acc[4][4][4];
#pragma unroll
    for (int i = 0; i < 4; i++)
#pragma unroll
        for (int j = 0; j < 4; j++)
#pragma unroll
            for (int q = 0; q < 4; q++) acc[i][j][q] = 0.f;

    uint32_t aOff = (uint32_t)((m0 + (lane & 15)) * (TSTRIDE * 2) + (lane >> 4) * 16);
    uint32_t bOff = (uint32_t)((n0 + (lane & 7) + (lane >> 4) * 8) * (TSTRIDE * 2) + ((lane >> 3) & 1) * 16);

#pragma unroll
    for (int ks = 0; ks < 8; ks++) {
        uint32_t kByte = (uint32_t)(ks * 32);
        uint32_t ah[4][4], al[4][4], bh[4][2], bl[4][2];
#pragma unroll
        for (int i = 0; i < 4; i++) {
            uint32_t ad = sb + AHI_OFF + aOff + kByte + (uint32_t)(i * 16 * TSTRIDE * 2);
            LDMX4(ah[i][0], ah[i][1], ah[i][2], ah[i][3], ad);
        }
#pragma unroll
        for (int i = 0; i < 4; i++) {
            uint32_t ad = sb + ALO_OFF + aOff + kByte + (uint32_t)(i * 16 * TSTRIDE * 2);
            LDMX4(al[i][0], al[i][1], al[i][2], al[i][3], ad);
        }
#pragma unroll
        for (int jj = 0; jj < 2; jj++) {
            uint32_t bd = sb + BHI_OFF + bOff + kByte + (uint32_t)(jj * 16 * TSTRIDE * 2);
            uint32_t r0, r1, r2, r3;
            LDMX4(r0, r1, r2, r3, bd);
            bh[2 * jj][0] = r0; bh[2 * jj][1] = r1;
            bh[2 * jj + 1][0] = r2; bh[2 * jj + 1][1] = r3;
            bd = sb + BLO_OFF + bOff + kByte + (uint32_t)(jj * 16 * TSTRIDE * 2);
            LDMX4(r0, r1, r2, r3, bd);
            bl[2 * jj][0] = r0; bl[2 * jj][1] = r1;
            bl[2 * jj + 1][0] = r2; bl[2 * jj + 1][1] = r3;
        }
#pragma unroll
        for (int i = 0; i < 4; i++)
#pragma unroll
            for (int j = 0; j < 4; j++) MMA16816(acc[i][j], ah[i], bh[j]);
#pragma unroll
        for (int i = 0; i < 4; i++)
#pragma unroll
            for (int j = 0; j < 4; j++) MMA16816(acc[i][j], ah[i], bl[j]);
#pragma unroll
        for (int i = 0; i < 4; i++)
#pragma unroll
            for (int j = 0; j < 4; j++) MMA16816(acc[i][j], al[i], bh[j]);
    }

    // ---- epilogue: bias, store, fused BN stats ----
    float* scs = (float*)(smem + STAT_OFF);
    float* scq = scs + 128;
    int rq = lane >> 2, cq = (lane & 3) * 2;
    const float* bs = (const float*)(smem + BIAS_OFF);

    float ps[4][2], pq[4][2];
#pragma unroll
    for (int j = 0; j < 4; j++) { ps[j][0] = ps[j][1] = 0.f; pq[j][0] = pq[j][1] = 0.f; }

#pragma unroll
    for (int i = 0; i < 4; i++) {
        int r0g = rowBase + m0 + i * 16 + rq;
#pragma unroll
        for (int j = 0; j < 4; j++) {
            int cg = n0 + j * 8 + cq;
            float bx = bs[cg], by = bs[cg + 1];
            if (r0g < NN) {
                float v0 = acc[i][j][0] + bx, v1 = acc[i][j][1] + by;
                *(float2*)(Y + (size_t)r0g * DD + cg) = make_float2(v0, v1);
                ps[j][0] += v0; pq[j][0] += v0 * v0;
                ps[j][1] += v1; pq[j][1] += v1 * v1;
            }
            if (r0g + 8 < NN) {
                float v2 = acc[i][j][2] + bx, v3 = acc[i][j][3] + by;
                *(float2*)(Y + (size_t)(r0g + 8) * DD + cg) = make_float2(v2, v3);
                ps[j][0] += v2; pq[j][0] += v2 * v2;
                ps[j][1] += v3; pq[j][1] += v3 * v3;
            }
        }
    }
#pragma unroll
    for (int j = 0; j < 4; j++)
#pragma unroll
        for (int c = 0; c < 2; c++) {
#pragma unroll
            for (int m = 4; m <= 16; m <<= 1) {
                ps[j][c] += __shfl_xor_sync(0xFFFFFFFFu, ps[j][c], m);
                pq[j][c] += __shfl_xor_sync(0xFFFFFFFFu, pq[j][c], m);
            }
        }
    if (rq == 0) {
#pragma unroll
        for (int j = 0; j < 4; j++)
#pragma unroll
            for (int c = 0; c < 2; c++) {
                atomicAdd(&scs[n0 + j * 8 + cq + c], ps[j][c]);
                atomicAdd(&scq[n0 + j * 8 + cq + c], pq[j][c]);
            }
    }
    __syncthreads();
    if (tid < 128) {
        atomicAdd(&colsum[tid], scs[tid]);
        atomicAdd(&colsq[tid],  scq[tid]);
    }
}

// ---------------- BN scale/shift (reads stats bank, then zeroes it) ----------------
__global__ void bn_stats_k(float* __restrict__ cs, float* __restrict__ cq,
                           const float* __restrict__ g, const float* __restrict__ b,
                           float* __restrict__ sOut, float* __restrict__ tOut)
{
    int d = threadIdx.x;
    float su = cs[d], sq = cq[d];
    float mu  = su * (1.0f / NN);
    float var = sq * (1.0f / NN) - mu * mu;
    float sc  = g[d] * rsqrtf(var + 1e-5f);
    sOut[d] = sc;
    tOut[d] = b[d] - mu * sc;
    cs[d] = 0.f;      // self-zero (globals start zeroed; invariant across replays)
    cq[d] = 0.f;
}

// ---------------- final output: out = y2*s2+t2 (no relu, last layer) ----------------
__global__ void finalize_k(float* __restrict__ out) {
    int i = blockIdx.x * 256 + threadIdx.x;   // 6250 * 256 = NN*DD/4
    int d4 = (i * 4) & 127;
    float4 v = ((const float4*)g_y2)[i];
    float4 s = *(const float4*)(g_s2 + d4);
    float4 t = *(const float4*)(g_t2 + d4);
    v.x = fmaf(v.x, s.x, t.x);
    v.y = fmaf(v.y, s.y, t.y);
    v.z = fmaf(v.z, s.z, t.z);
    v.w = fmaf(v.w, s.w, t.w);
    ((float4*)out)[i] = v;
}

extern "C" void kernel_launch(void* const* d_in, const int* in_sizes, int n_in,
                              void* d_out, int out_size)
{
    const float* x    = (const float*)d_in[0];
    const int*   ei32 = (const int*)d_in[1];
    const float* eps  = (const float*)d_in[2];
    const float* W1   = (const float*)d_in[3];
    const float* b1   = (const float*)d_in[4];
    const float* bn1g = (const float*)d_in[5];
    const float* bn1b = (const float*)d_in[6];
    const float* W2   = (const float*)d_in[7];
    const float* b2   = (const float*)d_in[8];
    const float* bn2g = (const float*)d_in[9];
    const float* bn2b = (const float*)d_in[10];

    float *y1p, *y2p, *statsp, *s1p, *t1p, *s2p, *t2p;
    unsigned short *whip, *wlop;
    cudaGetSymbolAddress((void**)&y1p,    g_y1);
    cudaGetSymbolAddress((void**)&y2p,    g_y2);
    cudaGetSymbolAddress((void**)&statsp, g_stats);
    cudaGetSymbolAddress((void**)&s1p,    g_s1);
    cudaGetSymbolAddress((void**)&t1p,    g_t1);
    cudaGetSymbolAddress((void**)&s2p,    g_s2);
    cudaGetSymbolAddress((void**)&t2p,    g_t2);
    cudaGetSymbolAddress((void**)&whip,   g_whi);
    cudaGetSymbolAddress((void**)&wlop,   g_wlo);

    cudaFuncSetAttribute((const void*)gemm_tc_k<1, 0>, cudaFuncAttributeMaxDynamicSharedMemorySize, GEMM_SMEM);
    cudaFuncSetAttribute((const void*)gemm_tc_k<1, 1>, cudaFuncAttributeMaxDynamicSharedMemorySize, GEMM_SMEM);
    cudaFuncSetAttribute((const void*)gemm_tc_k<2, 0>, cudaFuncAttributeMaxDynamicSharedMemorySize, GEMM_SMEM);

    const int gemmBlocks = (NN + 127) / 128;   // 391

    // one-time prep
    detect_k<<<1, 1>>>(ei32);
    wprep_k<<<384, 256>>>(W1, W2);
    zdeg_k<<<196, 256>>>();
    count_k<<<3125, 256>>>(ei32);
    scan1_k<<<49, 1024>>>();
    scan2_k<<<1, 1>>>();
    scan3_k<<<49, 1024>>>();
    fill_k<<<3125, 256>>>(ei32);

    for (int l = 0; l < 3; l++) {
        if (l == 0) {
            agg_k<0><<<6250, 256>>>(x);
            gemm_tc_k<1, 0><<<gemmBlocks, 256, GEMM_SMEM>>>(x, eps, l,
                whip + (size_t)l * 16384, wlop + (size_t)l * 16384,
                b1 + (size_t)l * DD, y1p, statsp, statsp + 128);
        } else {
            agg_k<1><<<6250, 256>>>(y2p);
            gemm_tc_k<1, 1><<<gemmBlocks, 256, GEMM_SMEM>>>(y2p, eps, l,
                whip + (size_t)l * 16384, wlop + (size_t)l * 16384,
                b1 + (size_t)l * DD, y1p, statsp, statsp + 128);
        }
        bn_stats_k<<<1, 128>>>(statsp, statsp + 128,
                               bn1g + (size_t)l * DD, bn1b + (size_t)l * DD, s1p, t1p);
        gemm_tc_k<2, 0><<<gemmBlocks, 256, GEMM_SMEM>>>(y1p, eps, l,
            whip + (size_t)(3 + l) * 16384, wlop + (size_t)(3 + l) * 16384,
            b2 + (size_t)l * DD, y2p, statsp + 256, statsp + 384);
        bn_stats_k<<<1, 128>>>(statsp + 256, statsp + 384,
                               bn2g + (size_t)l * DD, bn2b + (size_t)l * DD, s2p, t2p);
    }
    finalize_k<<<6250, 256>>>((float*)d_out);
}